// round 1
// baseline (speedup 1.0000x reference)
#include <cuda_runtime.h>
#include <math.h>

#define N_NODES 20000
#define N_EDGES 320000
#define C_      32
#define NE_     10
#define G_      64
#define NB_     8
#define HID_    64
#define RMAX    5.0f
#define TAB     4096

// ---------------- device scratch (static; no allocation) ----------------
__device__ float g_pos[N_NODES * 3];        // pos_noisy
__device__ float g_attrs[N_NODES * NE_];    // attrs_noisy
__device__ float g_scalar[N_NODES * C_];    // current scalar features
__device__ float g_pred[N_NODES * 13];
__device__ float g_Y[N_EDGES * 16];
__device__ float g_r[N_EDGES];
__device__ int   g_deg[N_NODES];
__device__ int   g_rowptr[N_NODES + 1];
__device__ int   g_cursor[N_NODES];
__device__ int   g_eidx[N_EDGES];           // active edges sorted by receiver
__device__ float g_rwtab[2 * TAB * 128];    // radial MLP lookup table per layer
__device__ float g_agg[N_NODES * 512];      // layout (n, k, c)
__device__ float g_feats[N_NODES * 512];    // layout (n, k, d)
__device__ float g_lacc[G_];
__device__ int   g_lcnt[G_];

// ---------------- init: zero deg + loss accumulators ----------------
__global__ void k_init() {
    int i = blockIdx.x * blockDim.x + threadIdx.x;
    if (i < N_NODES) g_deg[i] = 0;
    if (i < G_) { g_lacc[i] = 0.0f; g_lcnt[i] = 0; }
}

// ---------------- per-node: noisy pos/attrs + embedding ----------------
__global__ void k_node_init(const float* __restrict__ pos,
                            const float* __restrict__ attrs,
                            const float* __restrict__ eps,
                            const float* __restrict__ alpha_bar,
                            const float* __restrict__ W_embed,
                            const int* __restrict__ batch,
                            const int* __restrict__ t) {
    int n = blockIdx.x * blockDim.x + threadIdx.x;
    if (n >= N_NODES) return;
    int b = batch[n];
    int tt = t[b];
    float ab = alpha_bar[tt];
    float sa = sqrtf(ab), sb = sqrtf(1.0f - ab);
#pragma unroll
    for (int j = 0; j < 3; j++)
        g_pos[n * 3 + j] = sa * pos[n * 3 + j] + sb * eps[n * 13 + 10 + j];
    float an[10];
#pragma unroll
    for (int i = 0; i < 10; i++) {
        an[i] = sa * attrs[n * 10 + i] * 0.25f + sb * eps[n * 13 + i];
        g_attrs[n * 10 + i] = an[i];
    }
    float tf = (float)tt / 1000.0f;
#pragma unroll 4
    for (int c = 0; c < 32; c++) {
        float h = tf * W_embed[10 * 32 + c];
#pragma unroll
        for (int i = 0; i < 10; i++) h += an[i] * W_embed[i * 32 + c];
        g_scalar[n * 32 + c] = h;
    }
}

// ---------------- per-edge geometry: r, Y, active-degree ----------------
__global__ void k_geom(const int* __restrict__ ei, const float* __restrict__ shifts) {
    int e = blockIdx.x * blockDim.x + threadIdx.x;
    if (e >= N_EDGES) return;
    int s = ei[e], rc = ei[N_EDGES + e];
    float vx = g_pos[rc * 3 + 0] - g_pos[s * 3 + 0] + shifts[e * 3 + 0];
    float vy = g_pos[rc * 3 + 1] - g_pos[s * 3 + 1] + shifts[e * 3 + 1];
    float vz = g_pos[rc * 3 + 2] - g_pos[s * 3 + 2] + shifts[e * 3 + 2];
    float r = sqrtf(vx * vx + vy * vy + vz * vz + 1e-12f);
    g_r[e] = r;
    if (r >= RMAX) return;  // rw == 0 exactly (no bias, silu(0)=0): edge dead
    atomicAdd(&g_deg[rc], 1);
    float inv = 1.0f / r;
    float x = vx * inv, y = vy * inv, z = vz * inv;
    float xx = x * x, yy = y * y, zz = z * z;
    const float s3 = 1.7320508075688772f, s5 = 2.23606797749979f;
    const float s7 = 2.6457513110645906f, s15 = 3.872983346207417f;
    const float s105 = 10.246950765959598f;
    const float s35_8 = 2.0916500663351889f, s21_8 = 1.6201851746019651f;
    float4* Yp = (float4*)&g_Y[e * 16];
    Yp[0] = make_float4(1.0f, s3 * x, s3 * y, s3 * z);
    Yp[1] = make_float4(s15 * x * y, s15 * y * z, 0.5f * s5 * (3.0f * zz - 1.0f), s15 * x * z);
    Yp[2] = make_float4(0.5f * s15 * (xx - yy), s35_8 * y * (3.0f * xx - yy),
                        s105 * x * y * z, s21_8 * y * (5.0f * zz - 1.0f));
    Yp[3] = make_float4(0.5f * s7 * (5.0f * zz * z - 3.0f * z), s21_8 * x * (5.0f * zz - 1.0f),
                        0.5f * s105 * z * (xx - yy), s35_8 * x * (xx - 3.0f * yy));
}

// ---------------- single-block exclusive scan of degrees ----------------
__global__ void k_scan() {
    __shared__ int sh[1024];
    int t = threadIdx.x;
    const int CH = (N_NODES + 1023) / 1024;  // 20
    int beg = t * CH, end = min(beg + CH, N_NODES);
    int s = 0;
    for (int i = beg; i < end; i++) s += g_deg[i];
    sh[t] = s;
    __syncthreads();
    for (int off = 1; off < 1024; off <<= 1) {
        int v = (t >= off) ? sh[t - off] : 0;
        __syncthreads();
        sh[t] += v;
        __syncthreads();
    }
    int run = sh[t] - s;  // exclusive prefix
    for (int i = beg; i < end; i++) {
        g_rowptr[i] = run;
        g_cursor[i] = run;
        run += g_deg[i];
    }
    if (t == 1023) g_rowptr[N_NODES] = sh[1023];
}

__global__ void k_fill(const int* __restrict__ ei) {
    int e = blockIdx.x * blockDim.x + threadIdx.x;
    if (e >= N_EDGES) return;
    if (g_r[e] >= RMAX) return;
    int rc = ei[N_EDGES + e];
    int p = atomicAdd(&g_cursor[rc], 1);
    g_eidx[p] = e;
}

// ---------------- radial MLP lookup table (both layers) ----------------
__global__ void k_table(const float* __restrict__ W_r1, const float* __restrict__ W_r2) {
    int idx = blockIdx.x;
    int l = idx >> 12;
    int i = idx & (TAB - 1);
    int j = threadIdx.x;  // 0..63
    __shared__ float hid[64];
    float r = (float)i * (RMAX / (float)(TAB - 1));
    float rc = fmaxf(r, 1e-9f);
    float xr = r / RMAX;
    float xr2 = xr * xr;
    float xr6 = xr2 * xr2 * xr2;
    float f = 1.0f - 28.0f * xr6 + 48.0f * xr6 * xr - 21.0f * xr6 * xr2;
    if (xr >= 1.0f) f = 0.0f;
    const float amp = 0.6324555320336759f;  // sqrt(2/5)
    const float PI_ = 3.14159265358979323846f;
    float ef[8];
#pragma unroll
    for (int nb = 0; nb < 8; nb++)
        ef[nb] = amp * sinf((float)(nb + 1) * PI_ * rc / RMAX) / rc * f;
    float h = 0.0f;
#pragma unroll
    for (int i0 = 0; i0 < 8; i0++) h += ef[i0] * W_r1[l * 512 + i0 * 64 + j];
    hid[j] = h / (1.0f + expf(-h));  // silu
    __syncthreads();
#pragma unroll
    for (int rep = 0; rep < 2; rep++) {
        int o = j + rep * 64;
        float acc = 0.0f;
#pragma unroll 8
        for (int h0 = 0; h0 < 64; h0++) acc += hid[h0] * W_r2[l * 8192 + h0 * 128 + o];
        g_rwtab[(l * TAB + i) * 128 + o] = acc;
    }
}

// ---------------- aggregation: warp per receiver node, lane = channel ----------------
#define YK(k) __shfl_sync(0xffffffffu, yv, (k))
__global__ void k_agg(int layer, const int* __restrict__ ei) {
    int warp = threadIdx.x >> 5, lane = threadIdx.x & 31;
    int n = blockIdx.x * 4 + warp;  // grid = N/4 exact
    float acc[16];
#pragma unroll
    for (int k = 0; k < 16; k++) acc[k] = 0.0f;
    int beg = g_rowptr[n], end = g_rowptr[n + 1];
    const float* tab = g_rwtab + layer * TAB * 128;
    for (int p = beg; p < end; p++) {
        int e = g_eidx[p];
        int s = ei[e];
        float sc = g_scalar[s * 32 + lane];
        float r = g_r[e];
        float x = r * ((float)(TAB - 1) / RMAX);
        int i0 = min((int)x, TAB - 2);
        float fr = x - (float)i0;
        float4 a = *((const float4*)(tab + i0 * 128) + lane);
        float4 b = *((const float4*)(tab + (i0 + 1) * 128) + lane);
        float m0 = sc * (a.x + fr * (b.x - a.x));
        float m1 = sc * (a.y + fr * (b.y - a.y));
        float m2 = sc * (a.z + fr * (b.z - a.z));
        float m3 = sc * (a.w + fr * (b.w - a.w));
        float yv = (lane < 16) ? g_Y[e * 16 + lane] : 0.0f;
        acc[0]  += m0 * YK(0);
        acc[1]  += m1 * YK(1);  acc[2]  += m1 * YK(2);  acc[3]  += m1 * YK(3);
        acc[4]  += m2 * YK(4);  acc[5]  += m2 * YK(5);  acc[6]  += m2 * YK(6);
        acc[7]  += m2 * YK(7);  acc[8]  += m2 * YK(8);
        acc[9]  += m3 * YK(9);  acc[10] += m3 * YK(10); acc[11] += m3 * YK(11);
        acc[12] += m3 * YK(12); acc[13] += m3 * YK(13); acc[14] += m3 * YK(14);
        acc[15] += m3 * YK(15);
    }
#pragma unroll
    for (int k = 0; k < 16; k++)
        g_agg[n * 512 + k * 32 + lane] = acc[k] * 0.0625f;  // / AVG_NEIGH
}

// ---------------- mix: feats[n,d,k] = sum_c agg[n,c,k] * W_mix[l,L[k],c,d] ----------------
__global__ void k_mix(int layer, const float* __restrict__ W_mix) {
    int gw = (blockIdx.x * blockDim.x + threadIdx.x) >> 5;
    int lane = threadIdx.x & 31;
    if (gw >= 16 * (N_NODES / 4)) return;
    int k = gw & 15;
    int n0 = (gw >> 4) * 4;
    int lm = (k == 0) ? 0 : (k < 4) ? 1 : (k < 9) ? 2 : 3;
    const float* W = W_mix + layer * 4096 + lm * 1024;
    float a0 = g_agg[(n0 + 0) * 512 + k * 32 + lane];
    float a1 = g_agg[(n0 + 1) * 512 + k * 32 + lane];
    float a2 = g_agg[(n0 + 2) * 512 + k * 32 + lane];
    float a3 = g_agg[(n0 + 3) * 512 + k * 32 + lane];
    float f0 = 0, f1 = 0, f2 = 0, f3 = 0;
#pragma unroll
    for (int c = 0; c < 32; c++) {
        float w = __ldg(&W[c * 32 + lane]);
        f0 += __shfl_sync(0xffffffffu, a0, c) * w;
        f1 += __shfl_sync(0xffffffffu, a1, c) * w;
        f2 += __shfl_sync(0xffffffffu, a2, c) * w;
        f3 += __shfl_sync(0xffffffffu, a3, c) * w;
    }
    g_feats[(n0 + 0) * 512 + k * 32 + lane] = f0;
    g_feats[(n0 + 1) * 512 + k * 32 + lane] = f1;
    g_feats[(n0 + 2) * 512 + k * 32 + lane] = f2;
    g_feats[(n0 + 3) * 512 + k * 32 + lane] = f3;
}

// ---------------- node epilogue: poly, self-connect, scalar, readouts ----------------
__global__ void k_nodeout(int layer,
                          const float* __restrict__ W_prod,
                          const float* __restrict__ W_sc,
                          const float* __restrict__ W_ro_s,
                          const float* __restrict__ W_ro_v) {
    int warp = threadIdx.x >> 5, lane = threadIdx.x & 31;
    int n = blockIdx.x * 4 + warp;  // grid = N/4 exact
    float f[16];
#pragma unroll
    for (int k = 0; k < 16; k++) f[k] = g_feats[n * 512 + k * 32 + lane];
    float s = f[0];
    float p = W_prod[layer * 96 + lane]
            + W_prod[layer * 96 + 32 + lane] * s
            + W_prod[layer * 96 + 64 + lane] * s * s;
#pragma unroll
    for (int k = 0; k < 16; k++) f[k] *= p;
    if (layer == 0) {
        float scv = 0.0f;
#pragma unroll
        for (int i = 0; i < 10; i++) scv += g_attrs[n * 10 + i] * W_sc[i * 32 + lane];
        f[0] += scv;
    }
    g_scalar[n * 32 + lane] = f[0];
#pragma unroll
    for (int j = 0; j < 10; j++) {
        float v = f[0] * W_ro_s[layer * 320 + lane * 10 + j];
#pragma unroll
        for (int o = 16; o; o >>= 1) v += __shfl_xor_sync(0xffffffffu, v, o);
        if (lane == 0) {
            if (layer == 0) g_pred[n * 13 + j] = v;
            else            g_pred[n * 13 + j] += v;
        }
    }
    float wv = W_ro_v[layer * 32 + lane];
#pragma unroll
    for (int m = 0; m < 3; m++) {
        float v = f[1 + m] * wv;
#pragma unroll
        for (int o = 16; o; o >>= 1) v += __shfl_xor_sync(0xffffffffu, v, o);
        if (lane == 0) {
            if (layer == 0) g_pred[n * 13 + 10 + m] = v;
            else            g_pred[n * 13 + 10 + m] += v;
        }
    }
}

// ---------------- loss ----------------
__global__ void k_loss(const float* __restrict__ eps, const int* __restrict__ batch) {
    int n = blockIdx.x * blockDim.x + threadIdx.x;
    if (n >= N_NODES) return;
    float e2 = 0.0f;
#pragma unroll
    for (int j = 0; j < 13; j++) {
        float d = g_pred[n * 13 + j] - eps[n * 13 + j];
        e2 += d * d;
    }
    int g = batch[n];
    atomicAdd(&g_lacc[g], e2);
    atomicAdd(&g_lcnt[g], 1);
}

__global__ void k_final(float* __restrict__ out) {
    int g = threadIdx.x;
    if (g < G_) {
        float nn = fmaxf((float)g_lcnt[g], 1.0f);
        out[g] = 0.5f * g_lacc[g] / (nn * 13.0f);
    }
}

// ---------------- launcher ----------------
extern "C" void kernel_launch(void* const* d_in, const int* in_sizes, int n_in,
                              void* d_out, int out_size) {
    (void)in_sizes; (void)n_in; (void)out_size;
    const float* pos     = (const float*)d_in[0];
    const float* attrs   = (const float*)d_in[1];
    const float* shifts  = (const float*)d_in[2];
    const float* eps     = (const float*)d_in[3];
    const float* alpha   = (const float*)d_in[4];
    const float* W_embed = (const float*)d_in[5];
    const float* W_r1    = (const float*)d_in[6];
    const float* W_r2    = (const float*)d_in[7];
    const float* W_mix   = (const float*)d_in[8];
    const float* W_sc    = (const float*)d_in[9];
    const float* W_prod  = (const float*)d_in[10];
    const float* W_ro_s  = (const float*)d_in[11];
    const float* W_ro_v  = (const float*)d_in[12];
    const int*   ei      = (const int*)d_in[13];
    const int*   batch   = (const int*)d_in[14];
    const int*   t       = (const int*)d_in[15];
    float* out = (float*)d_out;

    k_init<<<(N_NODES + 255) / 256, 256>>>();
    k_node_init<<<(N_NODES + 255) / 256, 256>>>(pos, attrs, eps, alpha, W_embed, batch, t);
    k_geom<<<(N_EDGES + 255) / 256, 256>>>(ei, shifts);
    k_scan<<<1, 1024>>>();
    k_fill<<<(N_EDGES + 255) / 256, 256>>>(ei);
    k_table<<<2 * TAB, 64>>>(W_r1, W_r2);
    for (int l = 0; l < 2; l++) {
        k_agg<<<N_NODES / 4, 128>>>(l, ei);
        k_mix<<<(16 * (N_NODES / 4) * 32) / 256, 256>>>(l, W_mix);
        k_nodeout<<<N_NODES / 4, 128>>>(l, W_prod, W_sc, W_ro_s, W_ro_v);
    }
    k_loss<<<(N_NODES + 255) / 256, 256>>>(eps, batch);
    k_final<<<1, 64>>>(out);
}

// round 2
// speedup vs baseline: 2.1299x; 2.1299x over previous
#include <cuda_runtime.h>
#include <cuda_fp16.h>
#include <math.h>

#define N_NODES 20000
#define N_EDGES 320000
#define C_      32
#define NE_     10
#define G_      64
#define RMAX    5.0f
#define TAB     4096
#define NSCB    79          // ceil(20000/256)

// ---------------- device scratch (static; no allocation) ----------------
__device__ float  g_pos[N_NODES * 3];
__device__ float  g_attrs[N_NODES * NE_];
__device__ float  g_scalar[N_NODES * C_];
__device__ float  g_pred[N_NODES * 13];
__device__ float  g_r[N_EDGES];
__device__ float4 g_vt[N_EDGES];            // (vx,vy,vz,r) for active edges only
__device__ int    g_deg[N_NODES];
__device__ int    g_rowptr[N_NODES + 1];
__device__ int    g_cursor[N_NODES];
__device__ int    g_part[NSCB];
__device__ int    g_poff[NSCB];
__device__ int    c_s[N_EDGES];             // compact: sender
__device__ float4 c_u[N_EDGES];             // compact: (ux,uy,uz, r*(TAB-1)/RMAX)
__device__ float  g_rwtab[2 * TAB * 128];   // fp32 table (temp)
__device__ __half2 g_tabh[2 * TAB * 128];   // packed (value, delta)
__device__ float  g_lacc[G_];
__device__ int    g_lcnt[G_];

// ---------------- tiny init ----------------
__global__ void k_init0() {
    int i = threadIdx.x;
    if (i < G_) { g_lacc[i] = 0.0f; g_lcnt[i] = 0; }
}

// ---------------- per-node: noisy pos/attrs + embedding (+deg zero) ----------------
__global__ void k_node_init(const float* __restrict__ pos,
                            const float* __restrict__ attrs,
                            const float* __restrict__ eps,
                            const float* __restrict__ alpha_bar,
                            const float* __restrict__ W_embed,
                            const int* __restrict__ batch,
                            const int* __restrict__ t) {
    int n = blockIdx.x * blockDim.x + threadIdx.x;
    if (n >= N_NODES) return;
    g_deg[n] = 0;
    int b = batch[n];
    int tt = t[b];
    float ab = alpha_bar[tt];
    float sa = sqrtf(ab), sb = sqrtf(1.0f - ab);
#pragma unroll
    for (int j = 0; j < 3; j++)
        g_pos[n * 3 + j] = sa * pos[n * 3 + j] + sb * eps[n * 13 + 10 + j];
    float an[10];
#pragma unroll
    for (int i = 0; i < 10; i++) {
        an[i] = sa * attrs[n * 10 + i] * 0.25f + sb * eps[n * 13 + i];
        g_attrs[n * 10 + i] = an[i];
    }
    float tf = (float)tt / 1000.0f;
#pragma unroll 4
    for (int c = 0; c < 32; c++) {
        float h = tf * W_embed[10 * 32 + c];
#pragma unroll
        for (int i = 0; i < 10; i++) h += an[i] * W_embed[i * 32 + c];
        g_scalar[n * 32 + c] = h;
    }
}

// ---------------- per-edge geometry: r, deg, raw vector ----------------
__global__ void k_geom(const int* __restrict__ ei, const float* __restrict__ shifts) {
    int e = blockIdx.x * blockDim.x + threadIdx.x;
    if (e >= N_EDGES) return;
    int s = ei[e], rc = ei[N_EDGES + e];
    float vx = g_pos[rc * 3 + 0] - g_pos[s * 3 + 0] + shifts[e * 3 + 0];
    float vy = g_pos[rc * 3 + 1] - g_pos[s * 3 + 1] + shifts[e * 3 + 1];
    float vz = g_pos[rc * 3 + 2] - g_pos[s * 3 + 2] + shifts[e * 3 + 2];
    float r = sqrtf(vx * vx + vy * vy + vz * vz + 1e-12f);
    g_r[e] = r;
    if (r >= RMAX) return;
    atomicAdd(&g_deg[rc], 1);
    g_vt[e] = make_float4(vx, vy, vz, r);
}

// ---------------- 3-phase scan ----------------
__global__ void k_scanA() {
    __shared__ int sh[256];
    int tid = threadIdx.x;
    int i = blockIdx.x * 256 + tid;
    sh[tid] = (i < N_NODES) ? g_deg[i] : 0;
    __syncthreads();
    for (int off = 128; off; off >>= 1) {
        if (tid < off) sh[tid] += sh[tid + off];
        __syncthreads();
    }
    if (tid == 0) g_part[blockIdx.x] = sh[0];
}
__global__ void k_scanB() {
    __shared__ int sh[128];
    int tid = threadIdx.x;
    int v = (tid < NSCB) ? g_part[tid] : 0;
    sh[tid] = v;
    __syncthreads();
    for (int off = 1; off < 128; off <<= 1) {
        int u = (tid >= off) ? sh[tid - off] : 0;
        __syncthreads();
        sh[tid] += u;
        __syncthreads();
    }
    if (tid < NSCB) g_poff[tid] = sh[tid] - v;
    if (tid == 127) g_rowptr[N_NODES] = sh[127];
}
__global__ void k_scanC() {
    __shared__ int sh[256];
    int tid = threadIdx.x;
    int i = blockIdx.x * 256 + tid;
    int v = (i < N_NODES) ? g_deg[i] : 0;
    sh[tid] = v;
    __syncthreads();
    for (int off = 1; off < 256; off <<= 1) {
        int u = (tid >= off) ? sh[tid - off] : 0;
        __syncthreads();
        sh[tid] += u;
        __syncthreads();
    }
    if (i < N_NODES) {
        int excl = sh[tid] - v + g_poff[blockIdx.x];
        g_rowptr[i] = excl;
        g_cursor[i] = excl;
    }
}

// ---------------- compact active-edge records ----------------
__global__ void k_fill(const int* __restrict__ ei) {
    int e = blockIdx.x * blockDim.x + threadIdx.x;
    if (e >= N_EDGES) return;
    float r = g_r[e];
    if (r >= RMAX) return;
    float4 v = g_vt[e];
    int rc = ei[N_EDGES + e];
    int p = atomicAdd(&g_cursor[rc], 1);
    float inv = 1.0f / r;
    c_s[p] = ei[e];
    c_u[p] = make_float4(v.x * inv, v.y * inv, v.z * inv, r * ((float)(TAB - 1) / RMAX));
}

// ---------------- radial MLP lookup table ----------------
__global__ void k_table(const float* __restrict__ W_r1, const float* __restrict__ W_r2) {
    int idx = blockIdx.x;
    int l = idx >> 12;
    int i = idx & (TAB - 1);
    int j = threadIdx.x;  // 0..63
    __shared__ float hid[64];
    float r = (float)i * (RMAX / (float)(TAB - 1));
    float rc = fmaxf(r, 1e-9f);
    float xr = r / RMAX;
    float xr2 = xr * xr;
    float xr6 = xr2 * xr2 * xr2;
    float f = 1.0f - 28.0f * xr6 + 48.0f * xr6 * xr - 21.0f * xr6 * xr2;
    if (xr >= 1.0f) f = 0.0f;
    const float amp = 0.6324555320336759f;  // sqrt(2/5)
    const float PI_ = 3.14159265358979323846f;
    float ef[8];
#pragma unroll
    for (int nb = 0; nb < 8; nb++)
        ef[nb] = amp * sinf((float)(nb + 1) * PI_ * rc / RMAX) / rc * f;
    float h = 0.0f;
#pragma unroll
    for (int i0 = 0; i0 < 8; i0++) h += ef[i0] * W_r1[l * 512 + i0 * 64 + j];
    hid[j] = h / (1.0f + expf(-h));  // silu
    __syncthreads();
#pragma unroll
    for (int rep = 0; rep < 2; rep++) {
        int o = j + rep * 64;
        float acc = 0.0f;
#pragma unroll 8
        for (int h0 = 0; h0 < 64; h0++) acc += hid[h0] * W_r2[l * 8192 + h0 * 128 + o];
        g_rwtab[(l * TAB + i) * 128 + o] = acc;
    }
}

// pack (value, next-value - value) into half2
__global__ void k_tabpack() {
    int idx = blockIdx.x * blockDim.x + threadIdx.x;  // over 2*TAB*128
    int row = idx >> 7;
    int il = row & (TAB - 1);
    float a = g_rwtab[idx];
    float d = (il < TAB - 1) ? (g_rwtab[idx + 128] - a) : 0.0f;
    g_tabh[idx] = __floats2half2_rn(a, d);
}

// ---------------- fused layer: agg + mix + poly + readouts (+loss on last) ----------------
template <int LAYER>
__global__ void __launch_bounds__(128) k_layer(const float* __restrict__ W_mix,
                                               const float* __restrict__ W_prod,
                                               const float* __restrict__ W_sc,
                                               const float* __restrict__ W_ro_s,
                                               const float* __restrict__ W_ro_v,
                                               const float* __restrict__ eps,
                                               const int* __restrict__ batch) {
    __shared__ float Wsh[4096];  // W_mix[LAYER]: [4][32][32]
    for (int i = threadIdx.x; i < 4096; i += 128)
        Wsh[i] = W_mix[LAYER * 4096 + i];
    __syncthreads();

    int warp = threadIdx.x >> 5, lane = threadIdx.x & 31;
    int n = blockIdx.x * 4 + warp;  // grid = N/4 exact

    float acc[16];
#pragma unroll
    for (int k = 0; k < 16; k++) acc[k] = 0.0f;

    int beg = g_rowptr[n], end = g_rowptr[n + 1];
    const __half2* tab = g_tabh + LAYER * TAB * 128;

    for (int p = beg; p < end; p++) {
        int s = __ldg(&c_s[p]);
        float4 u = __ldg(&c_u[p]);
        float sc = g_scalar[s * 32 + lane];
        int i0 = (int)u.w;
        float fr = u.w - (float)i0;
        // one coalesced 512B row: 4 half2 (value,delta) pairs per lane
        float4 tv = __ldg((const float4*)(tab + i0 * 128) + lane);
        const __half2* hp = (const __half2*)&tv;
        float2 q0 = __half22float2(hp[0]);
        float2 q1 = __half22float2(hp[1]);
        float2 q2 = __half22float2(hp[2]);
        float2 q3 = __half22float2(hp[3]);
        float m0 = sc * fmaf(fr, q0.y, q0.x);
        float m1 = sc * fmaf(fr, q1.y, q1.x);
        float m2 = sc * fmaf(fr, q2.y, q2.x);
        float m3 = sc * fmaf(fr, q3.y, q3.x);
        // spherical harmonics inline
        float x = u.x, y = u.y, z = u.z;
        float xx = x * x, yy = y * y, zz = z * z;
        const float s3 = 1.7320508075688772f, s5 = 2.23606797749979f;
        const float s7 = 2.6457513110645906f, s15 = 3.872983346207417f;
        const float s105 = 10.246950765959598f;
        const float s35_8 = 2.0916500663351889f, s21_8 = 1.6201851746019651f;
        acc[0]  += m0;
        acc[1]  += m1 * (s3 * x);
        acc[2]  += m1 * (s3 * y);
        acc[3]  += m1 * (s3 * z);
        acc[4]  += m2 * (s15 * x * y);
        acc[5]  += m2 * (s15 * y * z);
        acc[6]  += m2 * (0.5f * s5 * (3.0f * zz - 1.0f));
        acc[7]  += m2 * (s15 * x * z);
        acc[8]  += m2 * (0.5f * s15 * (xx - yy));
        acc[9]  += m3 * (s35_8 * y * (3.0f * xx - yy));
        acc[10] += m3 * (s105 * x * y * z);
        acc[11] += m3 * (s21_8 * y * (5.0f * zz - 1.0f));
        acc[12] += m3 * (0.5f * s7 * (5.0f * zz * z - 3.0f * z));
        acc[13] += m3 * (s21_8 * x * (5.0f * zz - 1.0f));
        acc[14] += m3 * (0.5f * s105 * z * (xx - yy));
        acc[15] += m3 * (s35_8 * x * (xx - 3.0f * yy));
    }
#pragma unroll
    for (int k = 0; k < 16; k++) acc[k] *= 0.0625f;  // / AVG_NEIGH

    // mix: f[k][lane=d] = sum_c acc[k][c] * W_mix[lm(k)][c][d]
    float f[16];
#pragma unroll
    for (int k = 0; k < 16; k++) {
        int lm = (k == 0) ? 0 : (k < 4) ? 1 : (k < 9) ? 2 : 3;
        float fv = 0.0f;
#pragma unroll
        for (int c = 0; c < 32; c++)
            fv += __shfl_sync(0xffffffffu, acc[k], c) * Wsh[lm * 1024 + c * 32 + lane];
        f[k] = fv;
    }

    // poly
    float s0 = f[0];
    float p = fmaf(fmaf(W_prod[LAYER * 96 + 64 + lane], s0, W_prod[LAYER * 96 + 32 + lane]),
                   s0, W_prod[LAYER * 96 + lane]);
#pragma unroll
    for (int k = 0; k < 16; k++) f[k] *= p;

    if (LAYER == 0) {
        float scv = 0.0f;
#pragma unroll
        for (int i = 0; i < 10; i++) scv += g_attrs[n * 10 + i] * W_sc[i * 32 + lane];
        f[0] += scv;
    }
    g_scalar[n * 32 + lane] = f[0];

    // readouts (+ loss on final layer)
    float e2 = 0.0f;
#pragma unroll
    for (int j = 0; j < 10; j++) {
        float v = f[0] * W_ro_s[LAYER * 320 + lane * 10 + j];
#pragma unroll
        for (int o = 16; o; o >>= 1) v += __shfl_xor_sync(0xffffffffu, v, o);
        if (lane == 0) {
            if (LAYER == 0) g_pred[n * 13 + j] = v;
            else {
                float d = g_pred[n * 13 + j] + v - eps[n * 13 + j];
                e2 = fmaf(d, d, e2);
            }
        }
    }
    float wv = W_ro_v[LAYER * 32 + lane];
#pragma unroll
    for (int m = 0; m < 3; m++) {
        float v = f[1 + m] * wv;
#pragma unroll
        for (int o = 16; o; o >>= 1) v += __shfl_xor_sync(0xffffffffu, v, o);
        if (lane == 0) {
            if (LAYER == 0) g_pred[n * 13 + 10 + m] = v;
            else {
                float d = g_pred[n * 13 + 10 + m] + v - eps[n * 13 + 10 + m];
                e2 = fmaf(d, d, e2);
            }
        }
    }
    if (LAYER == 1 && lane == 0) {
        int g = batch[n];
        atomicAdd(&g_lacc[g], e2);
        atomicAdd(&g_lcnt[g], 1);
    }
}

__global__ void k_final(float* __restrict__ out) {
    int g = threadIdx.x;
    if (g < G_) {
        float nn = fmaxf((float)g_lcnt[g], 1.0f);
        out[g] = 0.5f * g_lacc[g] / (nn * 13.0f);
    }
}

// ---------------- launcher ----------------
extern "C" void kernel_launch(void* const* d_in, const int* in_sizes, int n_in,
                              void* d_out, int out_size) {
    (void)in_sizes; (void)n_in; (void)out_size;
    const float* pos     = (const float*)d_in[0];
    const float* attrs   = (const float*)d_in[1];
    const float* shifts  = (const float*)d_in[2];
    const float* eps     = (const float*)d_in[3];
    const float* alpha   = (const float*)d_in[4];
    const float* W_embed = (const float*)d_in[5];
    const float* W_r1    = (const float*)d_in[6];
    const float* W_r2    = (const float*)d_in[7];
    const float* W_mix   = (const float*)d_in[8];
    const float* W_sc    = (const float*)d_in[9];
    const float* W_prod  = (const float*)d_in[10];
    const float* W_ro_s  = (const float*)d_in[11];
    const float* W_ro_v  = (const float*)d_in[12];
    const int*   ei      = (const int*)d_in[13];
    const int*   batch   = (const int*)d_in[14];
    const int*   t       = (const int*)d_in[15];
    float* out = (float*)d_out;

    k_init0<<<1, 64>>>();
    k_node_init<<<(N_NODES + 255) / 256, 256>>>(pos, attrs, eps, alpha, W_embed, batch, t);
    k_geom<<<(N_EDGES + 255) / 256, 256>>>(ei, shifts);
    k_scanA<<<NSCB, 256>>>();
    k_scanB<<<1, 128>>>();
    k_scanC<<<NSCB, 256>>>();
    k_fill<<<(N_EDGES + 255) / 256, 256>>>(ei);
    k_table<<<2 * TAB, 64>>>(W_r1, W_r2);
    k_tabpack<<<(2 * TAB * 128) / 256, 256>>>();
    k_layer<0><<<N_NODES / 4, 128>>>(W_mix, W_prod, W_sc, W_ro_s, W_ro_v, eps, batch);
    k_layer<1><<<N_NODES / 4, 128>>>(W_mix, W_prod, W_sc, W_ro_s, W_ro_v, eps, batch);
    k_final<<<1, 64>>>(out);
}

// round 3
// speedup vs baseline: 2.4773x; 1.1631x over previous
#include <cuda_runtime.h>
#include <cuda_fp16.h>
#include <math.h>

#define N_NODES 20000
#define N_EDGES 320000
#define G_      64
#define RMAX    5.0f
#define TAB     4096
#define NSCB    79          // ceil(20000/256)

// ---------------- device scratch (static; no allocation) ----------------
__device__ float  g_pos[N_NODES * 3];
__device__ float  g_attrs[N_NODES * 10];
__device__ float  g_scalar[N_NODES * 32];
__device__ float  g_pred[N_NODES * 13];
__device__ float4 g_vt[N_EDGES];            // (ux,uy,uz, tabcoord); tabcoord>=4095 => inactive
__device__ int    g_deg[N_NODES];
__device__ int    g_rowptr[N_NODES + 1];
__device__ int    g_cursor[N_NODES];
__device__ int    g_part[NSCB];
__device__ int    g_poff[NSCB];
__device__ int    g_tick;
__device__ int    g_done;
__device__ int    c_s[N_EDGES];             // compact: sender
__device__ float4 c_u[N_EDGES];             // compact: (ux,uy,uz, tabcoord)
__device__ float  g_rwtab[2 * TAB * 64];    // fp32 table (temp): [l][i][c*2+lsub]
__device__ __half2 g_tabh[2 * TAB * 64];    // packed (value, delta), scales folded
__device__ float  g_lacc[G_];
__device__ int    g_lcnt[G_];

// ---------------- per-node init: noise, embedding, counters ----------------
__global__ void k_node_init(const float* __restrict__ pos,
                            const float* __restrict__ attrs,
                            const float* __restrict__ eps,
                            const float* __restrict__ alpha_bar,
                            const float* __restrict__ W_embed,
                            const int* __restrict__ batch,
                            const int* __restrict__ t) {
    int n = blockIdx.x * blockDim.x + threadIdx.x;
    if (n >= N_NODES) return;
    if (n < G_) { g_lacc[n] = 0.0f; g_lcnt[n] = 0; }
    if (n == 0) { g_tick = 0; g_done = 0; }
    g_deg[n] = 0;
    int b = batch[n];
    int tt = t[b];
    float ab = alpha_bar[tt];
    float sa = sqrtf(ab), sb = sqrtf(1.0f - ab);
#pragma unroll
    for (int j = 0; j < 3; j++)
        g_pos[n * 3 + j] = sa * pos[n * 3 + j] + sb * eps[n * 13 + 10 + j];
    float an[10];
#pragma unroll
    for (int i = 0; i < 10; i++) {
        an[i] = sa * attrs[n * 10 + i] * 0.25f + sb * eps[n * 13 + i];
        g_attrs[n * 10 + i] = an[i];
    }
    float tf = (float)tt / 1000.0f;
#pragma unroll 4
    for (int c = 0; c < 32; c++) {
        float h = tf * W_embed[10 * 32 + c];
#pragma unroll
        for (int i = 0; i < 10; i++) h += an[i] * W_embed[i * 32 + c];
        g_scalar[n * 32 + c] = h;
    }
}

// ---------------- per-edge geometry ----------------
__global__ void k_geom(const int* __restrict__ ei, const float* __restrict__ shifts) {
    int e = blockIdx.x * blockDim.x + threadIdx.x;
    if (e >= N_EDGES) return;
    int s = ei[e], rc = ei[N_EDGES + e];
    float vx = g_pos[rc * 3 + 0] - g_pos[s * 3 + 0] + shifts[e * 3 + 0];
    float vy = g_pos[rc * 3 + 1] - g_pos[s * 3 + 1] + shifts[e * 3 + 1];
    float vz = g_pos[rc * 3 + 2] - g_pos[s * 3 + 2] + shifts[e * 3 + 2];
    float r = sqrtf(vx * vx + vy * vy + vz * vz + 1e-12f);
    float inv = 1.0f / r;
    float tc = r * ((float)(TAB - 1) / RMAX);   // >= 4095 iff r >= RMAX
    g_vt[e] = make_float4(vx * inv, vy * inv, vz * inv, tc);
    if (r < RMAX) atomicAdd(&g_deg[rc], 1);
}

// ---------------- scan phase A (+ fused partial-scan by last block) ----------------
__global__ void k_scanA() {
    __shared__ int sh[256];
    __shared__ int is_last;
    int tid = threadIdx.x;
    int i = blockIdx.x * 256 + tid;
    sh[tid] = (i < N_NODES) ? g_deg[i] : 0;
    __syncthreads();
    for (int off = 128; off; off >>= 1) {
        if (tid < off) sh[tid] += sh[tid + off];
        __syncthreads();
    }
    if (tid == 0) {
        g_part[blockIdx.x] = sh[0];
        __threadfence();
        int old = atomicAdd(&g_tick, 1);
        is_last = (old == NSCB - 1);
    }
    __syncthreads();
    if (!is_last) return;
    // last block scans the 79 partials
    __shared__ int sp[128];
    int v = 0;
    if (tid < 128) {
        v = (tid < NSCB) ? __ldcg(&g_part[tid]) : 0;
        sp[tid] = v;
    }
    __syncthreads();
    for (int off = 1; off < 128; off <<= 1) {
        int u = (tid >= off && tid < 128) ? sp[tid - off] : 0;
        __syncthreads();
        if (tid < 128) sp[tid] += u;
        __syncthreads();
    }
    if (tid < NSCB) g_poff[tid] = sp[tid] - v;
    if (tid == 127) g_rowptr[N_NODES] = sp[127];
}

// ---------------- scan phase C: per-block local scan + offset ----------------
__global__ void k_scanC() {
    __shared__ int sh[256];
    int tid = threadIdx.x;
    int i = blockIdx.x * 256 + tid;
    int v = (i < N_NODES) ? g_deg[i] : 0;
    sh[tid] = v;
    __syncthreads();
    for (int off = 1; off < 256; off <<= 1) {
        int u = (tid >= off) ? sh[tid - off] : 0;
        __syncthreads();
        sh[tid] += u;
        __syncthreads();
    }
    if (i < N_NODES) {
        int excl = sh[tid] - v + g_poff[blockIdx.x];
        g_rowptr[i] = excl;
        g_cursor[i] = excl;
    }
}

// ---------------- compact active-edge records ----------------
__global__ void k_fill(const int* __restrict__ ei) {
    int e = blockIdx.x * blockDim.x + threadIdx.x;
    if (e >= N_EDGES) return;
    float4 v = g_vt[e];
    if (v.w >= (float)(TAB - 1)) return;
    int rc = ei[N_EDGES + e];
    int p = atomicAdd(&g_cursor[rc], 1);
    c_s[p] = ei[e];
    c_u[p] = v;
}

// ---------------- radial MLP lookup table (only l=0,1 columns survive) ----------------
__global__ void k_table(const float* __restrict__ W_r1, const float* __restrict__ W_r2) {
    int idx = blockIdx.x;
    int l = idx >> 12;
    int i = idx & (TAB - 1);
    int j = threadIdx.x;  // 0..63
    __shared__ float hid[64];
    float r = (float)i * (RMAX / (float)(TAB - 1));
    float rc = fmaxf(r, 1e-9f);
    float xr = r / RMAX;
    float xr2 = xr * xr;
    float xr6 = xr2 * xr2 * xr2;
    float f = 1.0f - 28.0f * xr6 + 48.0f * xr6 * xr - 21.0f * xr6 * xr2;
    if (xr >= 1.0f) f = 0.0f;
    const float amp = 0.6324555320336759f;  // sqrt(2/5)
    const float PI_ = 3.14159265358979323846f;
    float ef[8];
#pragma unroll
    for (int nb = 0; nb < 8; nb++)
        ef[nb] = amp * sinf((float)(nb + 1) * PI_ * rc / RMAX) / rc * f;
    float h = 0.0f;
#pragma unroll
    for (int i0 = 0; i0 < 8; i0++) h += ef[i0] * W_r1[l * 512 + i0 * 64 + j];
    hid[j] = h / (1.0f + expf(-h));  // silu
    __syncthreads();
    // output column for (c, lsub): c*4 + lsub, with c = j>>1, lsub = j&1
    int col = ((j >> 1) << 2) | (j & 1);
    float acc = 0.0f;
#pragma unroll 8
    for (int h0 = 0; h0 < 64; h0++) acc += hid[h0] * W_r2[l * 8192 + h0 * 128 + col];
    g_rwtab[(l * TAB + i) * 64 + j] = acc;
}

// pack (value, next-value) with scale folded: l0 -> 1/16, l1 -> sqrt(3)/16
__global__ void k_tabpack() {
    int idx = blockIdx.x * blockDim.x + threadIdx.x;  // over 2*TAB*64
    if (idx >= 2 * TAB * 64) return;
    int row = idx >> 6;
    int il = row & (TAB - 1);
    int j = idx & 63;
    float scale = (j & 1) ? 0.10825317547305482f : 0.0625f;  // sqrt(3)/16 : 1/16
    float a = g_rwtab[idx] * scale;
    float d = (il < TAB - 1) ? (g_rwtab[idx + 64] * scale - a) : 0.0f;
    g_tabh[idx] = __floats2half2_rn(a, d);
}

// ---------------- fused layer: agg(4 comps) + mix + poly + readouts ----------------
template <int LAYER>
__global__ void __launch_bounds__(256) k_layer(const float* __restrict__ W_mix,
                                               const float* __restrict__ W_prod,
                                               const float* __restrict__ W_sc,
                                               const float* __restrict__ W_ro_s,
                                               const float* __restrict__ W_ro_v,
                                               const float* __restrict__ eps,
                                               const int* __restrict__ batch,
                                               float* __restrict__ out) {
    __shared__ float Wsh[2048];  // W_mix[LAYER][0..1]: 2 x 32 x 32
    for (int i = threadIdx.x; i < 2048; i += 256)
        Wsh[i] = W_mix[LAYER * 4096 + i];
    __syncthreads();

    int warp = threadIdx.x >> 5, lane = threadIdx.x & 31;
    int n = blockIdx.x * 8 + warp;  // grid = N/8 exact

    float a0 = 0.0f, a1 = 0.0f, a2 = 0.0f, a3 = 0.0f;
    int beg = g_rowptr[n], end = g_rowptr[n + 1];
    const float2* tab = (const float2*)(g_tabh + LAYER * TAB * 64);

    for (int p = beg; p < end; p++) {
        int s = __ldg(&c_s[p]);
        float4 u = __ldg(&c_u[p]);
        float sc = g_scalar[s * 32 + lane];
        int i0 = (int)u.w;
        float fr = u.w - (float)i0;
        float2 tv = __ldg(tab + i0 * 32 + lane);  // 2 half2: (v0,d0),(v1,d1)
        const __half2* hp = (const __half2*)&tv;
        float2 q0 = __half22float2(hp[0]);
        float2 q1 = __half22float2(hp[1]);
        float m0 = sc * fmaf(fr, q0.y, q0.x);
        float m1 = sc * fmaf(fr, q1.y, q1.x);
        a0 += m0;
        a1 = fmaf(m1, u.x, a1);
        a2 = fmaf(m1, u.y, a2);
        a3 = fmaf(m1, u.z, a3);
    }

    // mix: f[d=lane] over c via shuffle broadcast
    float f0 = 0.0f, f1 = 0.0f, f2 = 0.0f, f3 = 0.0f;
#pragma unroll
    for (int c = 0; c < 32; c++) {
        float w0 = Wsh[c * 32 + lane];
        float w1 = Wsh[1024 + c * 32 + lane];
        f0 = fmaf(__shfl_sync(0xffffffffu, a0, c), w0, f0);
        f1 = fmaf(__shfl_sync(0xffffffffu, a1, c), w1, f1);
        f2 = fmaf(__shfl_sync(0xffffffffu, a2, c), w1, f2);
        f3 = fmaf(__shfl_sync(0xffffffffu, a3, c), w1, f3);
    }

    // poly (depends on pre-self-connect scalar feat)
    float s0 = f0;
    float p = fmaf(fmaf(W_prod[LAYER * 96 + 64 + lane], s0, W_prod[LAYER * 96 + 32 + lane]),
                   s0, W_prod[LAYER * 96 + lane]);
    f0 *= p; f1 *= p; f2 *= p; f3 *= p;

    if (LAYER == 0) {
        float scv = 0.0f;
#pragma unroll
        for (int i = 0; i < 10; i++) scv += g_attrs[n * 10 + i] * W_sc[i * 32 + lane];
        f0 += scv;
    }
    g_scalar[n * 32 + lane] = f0;

    // readouts (+ loss on final layer)
    float e2 = 0.0f;
#pragma unroll
    for (int j = 0; j < 10; j++) {
        float v = f0 * W_ro_s[LAYER * 320 + lane * 10 + j];
#pragma unroll
        for (int o = 16; o; o >>= 1) v += __shfl_xor_sync(0xffffffffu, v, o);
        if (lane == 0) {
            if (LAYER == 0) g_pred[n * 13 + j] = v;
            else {
                float d = g_pred[n * 13 + j] + v - eps[n * 13 + j];
                e2 = fmaf(d, d, e2);
            }
        }
    }
    float wv = W_ro_v[LAYER * 32 + lane];
#pragma unroll
    for (int m = 0; m < 3; m++) {
        float fm = (m == 0) ? f1 : (m == 1) ? f2 : f3;
        float v = fm * wv;
#pragma unroll
        for (int o = 16; o; o >>= 1) v += __shfl_xor_sync(0xffffffffu, v, o);
        if (lane == 0) {
            if (LAYER == 0) g_pred[n * 13 + 10 + m] = v;
            else {
                float d = g_pred[n * 13 + 10 + m] + v - eps[n * 13 + 10 + m];
                e2 = fmaf(d, d, e2);
            }
        }
    }
    if (LAYER == 1) {
        if (lane == 0) {
            int g = batch[n];
            atomicAdd(&g_lacc[g], e2);
            atomicAdd(&g_lcnt[g], 1);
        }
        // last-block ticket computes final output
        __shared__ int is_last;
        __syncthreads();
        if (threadIdx.x == 0) {
            __threadfence();
            int old = atomicAdd(&g_done, 1);
            is_last = (old == gridDim.x - 1);
        }
        __syncthreads();
        if (is_last && threadIdx.x < G_) {
            int g = threadIdx.x;
            float la = atomicAdd(&g_lacc[g], 0.0f);   // coherent read
            int   lc = atomicAdd(&g_lcnt[g], 0);
            float nn = fmaxf((float)lc, 1.0f);
            out[g] = 0.5f * la / (nn * 13.0f);
        }
    }
}

// ---------------- launcher ----------------
extern "C" void kernel_launch(void* const* d_in, const int* in_sizes, int n_in,
                              void* d_out, int out_size) {
    (void)in_sizes; (void)n_in; (void)out_size;
    const float* pos     = (const float*)d_in[0];
    const float* attrs   = (const float*)d_in[1];
    const float* shifts  = (const float*)d_in[2];
    const float* eps     = (const float*)d_in[3];
    const float* alpha   = (const float*)d_in[4];
    const float* W_embed = (const float*)d_in[5];
    const float* W_r1    = (const float*)d_in[6];
    const float* W_r2    = (const float*)d_in[7];
    const float* W_mix   = (const float*)d_in[8];
    const float* W_sc    = (const float*)d_in[9];
    const float* W_prod  = (const float*)d_in[10];
    const float* W_ro_s  = (const float*)d_in[11];
    const float* W_ro_v  = (const float*)d_in[12];
    const int*   ei      = (const int*)d_in[13];
    const int*   batch   = (const int*)d_in[14];
    const int*   t       = (const int*)d_in[15];
    float* out = (float*)d_out;

    k_node_init<<<(N_NODES + 255) / 256, 256>>>(pos, attrs, eps, alpha, W_embed, batch, t);
    k_geom<<<(N_EDGES + 255) / 256, 256>>>(ei, shifts);
    k_table<<<2 * TAB, 64>>>(W_r1, W_r2);
    k_tabpack<<<(2 * TAB * 64 + 255) / 256, 256>>>();
    k_scanA<<<NSCB, 256>>>();
    k_scanC<<<NSCB, 256>>>();
    k_fill<<<(N_EDGES + 255) / 256, 256>>>(ei);
    k_layer<0><<<N_NODES / 8, 256>>>(W_mix, W_prod, W_sc, W_ro_s, W_ro_v, eps, batch, out);
    k_layer<1><<<N_NODES / 8, 256>>>(W_mix, W_prod, W_sc, W_ro_s, W_ro_v, eps, batch, out);
}

// round 4
// speedup vs baseline: 2.5563x; 1.0319x over previous
#include <cuda_runtime.h>
#include <cuda_fp16.h>
#include <math.h>

#define N_NODES 20000
#define N_EDGES 320000
#define G_      64
#define RMAX    5.0f
#define TAB     2048
#define NBLK    444         // 148 SMs x 3 blocks guaranteed resident
#define NTHR    256
#define NWARP   (NBLK * 8)
#define NSCB    79          // ceil(20000/256)

// ---------------- device scratch (static; no allocation) ----------------
__device__ float  g_pos[N_NODES * 3];
__device__ float  g_attrs[N_NODES * 10];
__device__ float  g_scalar[N_NODES * 32];
__device__ float  g_pred[N_NODES * 13];
__device__ float4 g_vt[N_EDGES];            // (ux,uy,uz, tabcoord); tabcoord>=TAB-1 => inactive
__device__ int    g_deg[N_NODES];
__device__ int    g_rowptr[N_NODES + 1];
__device__ int    g_cursor[N_NODES];
__device__ int    g_part[NSCB];
__device__ int    c_s[N_EDGES];             // compact: sender
__device__ float4 c_u[N_EDGES];             // compact: (ux,uy,uz, tabcoord)
__device__ float  g_rwtab[2 * TAB * 64];    // fp32 table: [l][i][packed col]
__device__ __half2 g_tabh[2 * TAB * 64];    // packed (value, delta), scales folded
__device__ float  g_lacc[G_];
__device__ int    g_lcnt[G_];

// ---------------- grid barrier (all blocks resident) ----------------
__device__ unsigned g_barArr = 0;
__device__ unsigned g_barGen = 0;

__device__ __forceinline__ void gridbar() {
    __syncthreads();
    if (threadIdx.x == 0) {
        __threadfence();
        unsigned gen = *(volatile unsigned*)&g_barGen;
        unsigned old = atomicAdd(&g_barArr, 1u);
        if (old == NBLK - 1) {
            g_barArr = 0;
            __threadfence();
            atomicAdd(&g_barGen, 1u);
        } else {
            while (*(volatile unsigned*)&g_barGen == gen) __nanosleep(64);
        }
        __threadfence();
    }
    __syncthreads();
}

// ---------------- fused layer phase ----------------
__device__ __forceinline__ void layer_phase(int LAYER,
                                            float* Wsh,
                                            const float* __restrict__ W_mix,
                                            const float* __restrict__ W_prod,
                                            const float* __restrict__ W_sc,
                                            const float* __restrict__ W_ro_s,
                                            const float* __restrict__ W_ro_v,
                                            const float* __restrict__ eps,
                                            const int* __restrict__ batch) {
    for (int i = threadIdx.x; i < 2048; i += NTHR)
        Wsh[i] = W_mix[LAYER * 4096 + i];
    __syncthreads();

    int warp = threadIdx.x >> 5, lane = threadIdx.x & 31;
    const float2* tab = (const float2*)(g_tabh + LAYER * TAB * 64);

    for (int n = blockIdx.x * 8 + warp; n < N_NODES; n += NWARP) {
        float a0 = 0.0f, a1 = 0.0f, a2 = 0.0f, a3 = 0.0f;
        int beg = g_rowptr[n], end = g_rowptr[n + 1];
        for (int p = beg; p < end; p++) {
            int s = __ldg(&c_s[p]);
            float4 u = __ldg(&c_u[p]);
            float sc = g_scalar[s * 32 + lane];
            int i0 = (int)u.w;
            float fr = u.w - (float)i0;
            float2 tv = __ldg(tab + i0 * 32 + lane);  // 2x half2: (v0,d0),(v1,d1)
            const __half2* hp = (const __half2*)&tv;
            float2 q0 = __half22float2(hp[0]);
            float2 q1 = __half22float2(hp[1]);
            float m0 = sc * fmaf(fr, q0.y, q0.x);
            float m1 = sc * fmaf(fr, q1.y, q1.x);
            a0 += m0;
            a1 = fmaf(m1, u.x, a1);
            a2 = fmaf(m1, u.y, a2);
            a3 = fmaf(m1, u.z, a3);
        }

        // mix via shuffle broadcast
        float f0 = 0.0f, f1 = 0.0f, f2 = 0.0f, f3 = 0.0f;
#pragma unroll
        for (int c = 0; c < 32; c++) {
            float w0 = Wsh[c * 32 + lane];
            float w1 = Wsh[1024 + c * 32 + lane];
            f0 = fmaf(__shfl_sync(0xffffffffu, a0, c), w0, f0);
            f1 = fmaf(__shfl_sync(0xffffffffu, a1, c), w1, f1);
            f2 = fmaf(__shfl_sync(0xffffffffu, a2, c), w1, f2);
            f3 = fmaf(__shfl_sync(0xffffffffu, a3, c), w1, f3);
        }

        float s0 = f0;
        float p = fmaf(fmaf(W_prod[LAYER * 96 + 64 + lane], s0, W_prod[LAYER * 96 + 32 + lane]),
                       s0, W_prod[LAYER * 96 + lane]);
        f0 *= p; f1 *= p; f2 *= p; f3 *= p;

        if (LAYER == 0) {
            float scv = 0.0f;
#pragma unroll
            for (int i = 0; i < 10; i++) scv += g_attrs[n * 10 + i] * W_sc[i * 32 + lane];
            f0 += scv;
        }
        g_scalar[n * 32 + lane] = f0;

        float e2 = 0.0f;
#pragma unroll
        for (int j = 0; j < 10; j++) {
            float v = f0 * W_ro_s[LAYER * 320 + lane * 10 + j];
#pragma unroll
            for (int o = 16; o; o >>= 1) v += __shfl_xor_sync(0xffffffffu, v, o);
            if (lane == 0) {
                if (LAYER == 0) g_pred[n * 13 + j] = v;
                else {
                    float d = g_pred[n * 13 + j] + v - eps[n * 13 + j];
                    e2 = fmaf(d, d, e2);
                }
            }
        }
        float wv = W_ro_v[LAYER * 32 + lane];
#pragma unroll
        for (int m = 0; m < 3; m++) {
            float fm = (m == 0) ? f1 : (m == 1) ? f2 : f3;
            float v = fm * wv;
#pragma unroll
            for (int o = 16; o; o >>= 1) v += __shfl_xor_sync(0xffffffffu, v, o);
            if (lane == 0) {
                if (LAYER == 0) g_pred[n * 13 + 10 + m] = v;
                else {
                    float d = g_pred[n * 13 + 10 + m] + v - eps[n * 13 + 10 + m];
                    e2 = fmaf(d, d, e2);
                }
            }
        }
        if (LAYER == 1 && lane == 0) {
            int g = batch[n];
            atomicAdd(&g_lacc[g], e2);
            atomicAdd(&g_lcnt[g], 1);
        }
    }
}

// ---------------- the mega-kernel ----------------
__global__ void __launch_bounds__(NTHR, 3)
k_mega(const float* __restrict__ pos,
       const float* __restrict__ attrs,
       const float* __restrict__ shifts,
       const float* __restrict__ eps,
       const float* __restrict__ alpha_bar,
       const float* __restrict__ W_embed,
       const float* __restrict__ W_r1,
       const float* __restrict__ W_r2,
       const float* __restrict__ W_mix,
       const float* __restrict__ W_sc,
       const float* __restrict__ W_prod,
       const float* __restrict__ W_ro_s,
       const float* __restrict__ W_ro_v,
       const int* __restrict__ ei,
       const int* __restrict__ batch,
       const int* __restrict__ t,
       float* __restrict__ out) {
    __shared__ float smf[2048];   // union: table hid (256) / scan (256i) / Wsh (2048)
    int tid = threadIdx.x;
    int bid = blockIdx.x;
    int gtid = bid * NTHR + tid;

    // ======== P0: node init + fp32 radial table ========
    if (gtid < N_NODES) {
        int n = gtid;
        if (n < G_) { g_lacc[n] = 0.0f; g_lcnt[n] = 0; }
        g_deg[n] = 0;
        int b = batch[n];
        int tt = t[b];
        float ab = alpha_bar[tt];
        float sa = sqrtf(ab), sb = sqrtf(1.0f - ab);
#pragma unroll
        for (int j = 0; j < 3; j++)
            g_pos[n * 3 + j] = sa * pos[n * 3 + j] + sb * eps[n * 13 + 10 + j];
        float an[10];
#pragma unroll
        for (int i = 0; i < 10; i++) {
            an[i] = sa * attrs[n * 10 + i] * 0.25f + sb * eps[n * 13 + i];
            g_attrs[n * 10 + i] = an[i];
        }
        float tf = (float)tt / 1000.0f;
#pragma unroll 4
        for (int c = 0; c < 32; c++) {
            float h = tf * W_embed[10 * 32 + c];
#pragma unroll
            for (int i = 0; i < 10; i++) h += an[i] * W_embed[i * 32 + c];
            g_scalar[n * 32 + c] = h;
        }
    }
    // table: 4 rows per block-iteration (sub-groups of 64 threads)
    {
        int sub = tid >> 6;     // 0..3
        int j = tid & 63;       // hidden / output index
        for (int chunk = bid; chunk < (2 * TAB) / 4; chunk += NBLK) {
            __syncthreads();    // protect smf reuse
            int row = chunk * 4 + sub;
            int l = row >> 11;          // TAB=2048
            int i = row & (TAB - 1);
            float r = (float)i * (RMAX / (float)(TAB - 1));
            float rc = fmaxf(r, 1e-9f);
            float xr = r / RMAX;
            float xr2 = xr * xr;
            float xr6 = xr2 * xr2 * xr2;
            float f = 1.0f - 28.0f * xr6 + 48.0f * xr6 * xr - 21.0f * xr6 * xr2;
            if (xr >= 1.0f) f = 0.0f;
            const float amp = 0.6324555320336759f;  // sqrt(2/5)
            const float PI_ = 3.14159265358979323846f;
            float h = 0.0f;
#pragma unroll
            for (int nb = 0; nb < 8; nb++) {
                float efv = amp * sinf((float)(nb + 1) * PI_ * rc / RMAX) / rc * f;
                h += efv * W_r1[l * 512 + nb * 64 + j];
            }
            smf[sub * 64 + j] = h / (1.0f + expf(-h));  // silu
            __syncthreads();
            int col = ((j >> 1) << 2) | (j & 1);        // only l=0,1 outputs survive
            float acc = 0.0f;
#pragma unroll 8
            for (int h0 = 0; h0 < 64; h0++)
                acc += smf[sub * 64 + h0] * W_r2[l * 8192 + h0 * 128 + col];
            g_rwtab[row * 64 + j] = acc;
        }
    }
    gridbar();

    // ======== P1: edge geometry ========
    for (int e = gtid; e < N_EDGES; e += NBLK * NTHR) {
        int s = ei[e], rc = ei[N_EDGES + e];
        float vx = g_pos[rc * 3 + 0] - g_pos[s * 3 + 0] + shifts[e * 3 + 0];
        float vy = g_pos[rc * 3 + 1] - g_pos[s * 3 + 1] + shifts[e * 3 + 1];
        float vz = g_pos[rc * 3 + 2] - g_pos[s * 3 + 2] + shifts[e * 3 + 2];
        float r = sqrtf(vx * vx + vy * vy + vz * vz + 1e-12f);
        float inv = 1.0f / r;
        float tc = r * ((float)(TAB - 1) / RMAX);
        g_vt[e] = make_float4(vx * inv, vy * inv, vz * inv, tc);
        if (r < RMAX) atomicAdd(&g_deg[rc], 1);
    }
    gridbar();

    // ======== P2: scan partials (blocks < NSCB) || table pack (rest) ========
    if (bid < NSCB) {
        int* shi = (int*)smf;
        int i = bid * 256 + tid;
        shi[tid] = (i < N_NODES) ? g_deg[i] : 0;
        __syncthreads();
        for (int off = 128; off; off >>= 1) {
            if (tid < off) shi[tid] += shi[tid + off];
            __syncthreads();
        }
        if (tid == 0) g_part[bid] = shi[0];
    } else {
        int base = (bid - NSCB) * NTHR + tid;
        for (int idx = base; idx < 2 * TAB * 64; idx += (NBLK - NSCB) * NTHR) {
            int row = idx >> 6;
            int il = row & (TAB - 1);
            int j = idx & 63;
            float scale = (j & 1) ? 0.10825317547305482f : 0.0625f;  // sqrt3/16 : 1/16
            float a = g_rwtab[idx] * scale;
            float d = (il < TAB - 1) ? (g_rwtab[idx + 64] * scale - a) : 0.0f;
            g_tabh[idx] = __floats2half2_rn(a, d);
        }
    }
    gridbar();

    // ======== P3: per-chunk offsets + local scan (blocks < NSCB) ========
    if (bid < NSCB) {
        int* shi = (int*)smf;
        // block offset = sum of partials below bid (+ total for last rowptr)
        int v = (tid < NSCB) ? g_part[tid] : 0;
        int below = (tid < bid) ? v : 0;
#pragma unroll
        for (int o = 16; o; o >>= 1) below += __shfl_xor_sync(0xffffffffu, below, o);
        __shared__ int s_off[8], s_tot[8];
        int w = tid >> 5;
        if ((tid & 31) == 0) s_off[w] = below;
        int totp = v;
#pragma unroll
        for (int o = 16; o; o >>= 1) totp += __shfl_xor_sync(0xffffffffu, totp, o);
        if ((tid & 31) == 0) s_tot[w] = totp;
        __syncthreads();
        int blkoff = 0, total = 0;
#pragma unroll
        for (int q = 0; q < 8; q++) { blkoff += s_off[q]; total += s_tot[q]; }
        // local inclusive scan of this chunk's degrees
        int i = bid * 256 + tid;
        int dv = (i < N_NODES) ? g_deg[i] : 0;
        shi[tid] = dv;
        __syncthreads();
        for (int off = 1; off < 256; off <<= 1) {
            int u = (tid >= off) ? shi[tid - off] : 0;
            __syncthreads();
            shi[tid] += u;
            __syncthreads();
        }
        if (i < N_NODES) {
            int excl = shi[tid] - dv + blkoff;
            g_rowptr[i] = excl;
            g_cursor[i] = excl;
        }
        if (bid == NSCB - 1 && tid == 0) g_rowptr[N_NODES] = total;
    }
    gridbar();

    // ======== P4: CSR fill ========
    for (int e = gtid; e < N_EDGES; e += NBLK * NTHR) {
        float4 v = g_vt[e];
        if (v.w >= (float)(TAB - 1)) continue;
        int rc = ei[N_EDGES + e];
        int p = atomicAdd(&g_cursor[rc], 1);
        c_s[p] = ei[e];
        c_u[p] = v;
    }
    gridbar();

    // ======== P5: layer 0 ========
    layer_phase(0, smf, W_mix, W_prod, W_sc, W_ro_s, W_ro_v, eps, batch);
    gridbar();

    // ======== P6: layer 1 (+ loss) ========
    layer_phase(1, smf, W_mix, W_prod, W_sc, W_ro_s, W_ro_v, eps, batch);
    gridbar();

    // ======== P7: final output ========
    if (bid == 0 && tid < G_) {
        float nn = fmaxf((float)g_lcnt[tid], 1.0f);
        out[tid] = 0.5f * g_lacc[tid] / (nn * 13.0f);
    }
}

// ---------------- launcher ----------------
extern "C" void kernel_launch(void* const* d_in, const int* in_sizes, int n_in,
                              void* d_out, int out_size) {
    (void)in_sizes; (void)n_in; (void)out_size;
    k_mega<<<NBLK, NTHR>>>(
        (const float*)d_in[0],  (const float*)d_in[1],  (const float*)d_in[2],
        (const float*)d_in[3],  (const float*)d_in[4],  (const float*)d_in[5],
        (const float*)d_in[6],  (const float*)d_in[7],  (const float*)d_in[8],
        (const float*)d_in[9],  (const float*)d_in[10], (const float*)d_in[11],
        (const float*)d_in[12], (const int*)d_in[13],   (const int*)d_in[14],
        (const int*)d_in[15],   (float*)d_out);
}

// round 5
// speedup vs baseline: 2.6440x; 1.0343x over previous
#include <cuda_runtime.h>
#include <cuda_fp16.h>
#include <math.h>

#define N_NODES 20000
#define N_EDGES 320000
#define G_      64
#define RMAX    5.0f
#define TAB     2048
#define NBLK    444         // 148 SMs x 3 blocks guaranteed resident
#define NTHR    256
#define NWARP   (NBLK * 8)
#define NSCB    79          // ceil(20000/256)

// ---------------- device scratch (static; no allocation) ----------------
__device__ float4 g_pos4[N_NODES];          // (x,y,z,0) noisy positions
__device__ float  g_attrs[N_NODES * 10];
__device__ float  g_scalar[N_NODES * 32];
__device__ float  g_pred[N_NODES * 13];
__device__ float4 g_vt[N_EDGES];            // (ux,uy,uz, tabcoord); tabcoord>=TAB-1 => inactive
__device__ int    g_deg[N_NODES];
__device__ int    g_rowptr[N_NODES + 1];
__device__ int    g_cursor[N_NODES];
__device__ int    g_part[NSCB];
__device__ int    c_s[N_EDGES];             // compact: sender
__device__ float4 c_u[N_EDGES];             // compact: (ux,uy,uz, tabcoord)
__device__ float  g_rwtab[2 * TAB * 64];    // fp32 table: [l][i][packed col]
__device__ __half2 g_tabh[2 * TAB * 64];    // packed (value, delta), scales folded
__device__ float  g_lacc[G_];
__device__ int    g_lcnt[G_];

// ---------------- grid barrier (all blocks resident) ----------------
__device__ unsigned g_barArr = 0;
__device__ unsigned g_barGen = 0;

__device__ __forceinline__ void gridbar() {
    __syncthreads();
    if (threadIdx.x == 0) {
        __threadfence();
        unsigned gen = *(volatile unsigned*)&g_barGen;
        unsigned old = atomicAdd(&g_barArr, 1u);
        if (old == NBLK - 1) {
            g_barArr = 0;
            __threadfence();
            atomicAdd(&g_barGen, 1u);
        } else {
            while (*(volatile unsigned*)&g_barGen == gen) __nanosleep(64);
        }
        __threadfence();
    }
    __syncthreads();
}

// ---------------- fused layer phase ----------------
__device__ __forceinline__ void layer_phase(int LAYER,
                                            float* Wsh,
                                            const float* __restrict__ W_mix,
                                            const float* __restrict__ W_prod,
                                            const float* __restrict__ W_sc,
                                            const float* __restrict__ W_ro_s,
                                            const float* __restrict__ W_ro_v,
                                            const float* __restrict__ eps,
                                            const int* __restrict__ batch) {
    for (int i = threadIdx.x; i < 2048; i += NTHR)
        Wsh[i] = W_mix[LAYER * 4096 + i];
    __syncthreads();

    int warp = threadIdx.x >> 5, lane = threadIdx.x & 31;
    const float2* tab = (const float2*)(g_tabh + LAYER * TAB * 64);

    for (int n = blockIdx.x * 8 + warp; n < N_NODES; n += NWARP) {
        float a0 = 0.0f, a1 = 0.0f, a2 = 0.0f, a3 = 0.0f;
        int beg = g_rowptr[n], end = g_rowptr[n + 1];
        for (int p = beg; p < end; p++) {
            int s = __ldg(&c_s[p]);
            float4 u = __ldg(&c_u[p]);
            float sc = g_scalar[s * 32 + lane];
            int i0 = (int)u.w;
            float fr = u.w - (float)i0;
            float2 tv = __ldg(tab + i0 * 32 + lane);  // 2x half2: (v0,d0),(v1,d1)
            const __half2* hp = (const __half2*)&tv;
            float2 q0 = __half22float2(hp[0]);
            float2 q1 = __half22float2(hp[1]);
            float m0 = sc * fmaf(fr, q0.y, q0.x);
            float m1 = sc * fmaf(fr, q1.y, q1.x);
            a0 += m0;
            a1 = fmaf(m1, u.x, a1);
            a2 = fmaf(m1, u.y, a2);
            a3 = fmaf(m1, u.z, a3);
        }

        // mix via shuffle broadcast
        float f0 = 0.0f, f1 = 0.0f, f2 = 0.0f, f3 = 0.0f;
#pragma unroll
        for (int c = 0; c < 32; c++) {
            float w0 = Wsh[c * 32 + lane];
            float w1 = Wsh[1024 + c * 32 + lane];
            f0 = fmaf(__shfl_sync(0xffffffffu, a0, c), w0, f0);
            f1 = fmaf(__shfl_sync(0xffffffffu, a1, c), w1, f1);
            f2 = fmaf(__shfl_sync(0xffffffffu, a2, c), w1, f2);
            f3 = fmaf(__shfl_sync(0xffffffffu, a3, c), w1, f3);
        }

        float s0 = f0;
        float p = fmaf(fmaf(W_prod[LAYER * 96 + 64 + lane], s0, W_prod[LAYER * 96 + 32 + lane]),
                       s0, W_prod[LAYER * 96 + lane]);
        f0 *= p; f1 *= p; f2 *= p; f3 *= p;

        if (LAYER == 0) {
            float scv = 0.0f;
#pragma unroll
            for (int i = 0; i < 10; i++) scv += g_attrs[n * 10 + i] * W_sc[i * 32 + lane];
            f0 += scv;
        }
        g_scalar[n * 32 + lane] = f0;

        float e2 = 0.0f;
#pragma unroll
        for (int j = 0; j < 10; j++) {
            float v = f0 * W_ro_s[LAYER * 320 + lane * 10 + j];
#pragma unroll
            for (int o = 16; o; o >>= 1) v += __shfl_xor_sync(0xffffffffu, v, o);
            if (lane == 0) {
                if (LAYER == 0) g_pred[n * 13 + j] = v;
                else {
                    float d = g_pred[n * 13 + j] + v - eps[n * 13 + j];
                    e2 = fmaf(d, d, e2);
                }
            }
        }
        float wv = W_ro_v[LAYER * 32 + lane];
#pragma unroll
        for (int m = 0; m < 3; m++) {
            float fm = (m == 0) ? f1 : (m == 1) ? f2 : f3;
            float v = fm * wv;
#pragma unroll
            for (int o = 16; o; o >>= 1) v += __shfl_xor_sync(0xffffffffu, v, o);
            if (lane == 0) {
                if (LAYER == 0) g_pred[n * 13 + 10 + m] = v;
                else {
                    float d = g_pred[n * 13 + 10 + m] + v - eps[n * 13 + 10 + m];
                    e2 = fmaf(d, d, e2);
                }
            }
        }
        if (LAYER == 1 && lane == 0) {
            int g = batch[n];
            atomicAdd(&g_lacc[g], e2);
            atomicAdd(&g_lcnt[g], 1);
        }
    }
}

// ---------------- the mega-kernel ----------------
__global__ void __launch_bounds__(NTHR, 3)
k_mega(const float* __restrict__ pos,
       const float* __restrict__ attrs,
       const float* __restrict__ shifts,
       const float* __restrict__ eps,
       const float* __restrict__ alpha_bar,
       const float* __restrict__ W_embed,
       const float* __restrict__ W_r1,
       const float* __restrict__ W_r2,
       const float* __restrict__ W_mix,
       const float* __restrict__ W_sc,
       const float* __restrict__ W_prod,
       const float* __restrict__ W_ro_s,
       const float* __restrict__ W_ro_v,
       const int* __restrict__ ei,
       const int* __restrict__ batch,
       const int* __restrict__ t,
       float* __restrict__ out) {
    __shared__ float smf[2048];   // union: table hid+sincos / scan / Wsh
    int tid = threadIdx.x;
    int bid = blockIdx.x;
    int gtid = bid * NTHR + tid;

    // ======== P0: node init + fp32 radial table ========
    if (gtid < N_NODES) {
        int n = gtid;
        if (n < G_) { g_lacc[n] = 0.0f; g_lcnt[n] = 0; }
        g_deg[n] = 0;
        int b = batch[n];
        int tt = t[b];
        float ab = alpha_bar[tt];
        float sa = sqrtf(ab), sb = sqrtf(1.0f - ab);
        g_pos4[n] = make_float4(sa * pos[n * 3 + 0] + sb * eps[n * 13 + 10],
                                sa * pos[n * 3 + 1] + sb * eps[n * 13 + 11],
                                sa * pos[n * 3 + 2] + sb * eps[n * 13 + 12], 0.0f);
        float an[10];
#pragma unroll
        for (int i = 0; i < 10; i++) {
            an[i] = sa * attrs[n * 10 + i] * 0.25f + sb * eps[n * 13 + i];
            g_attrs[n * 10 + i] = an[i];
        }
        float tf = (float)tt / 1000.0f;
#pragma unroll 4
        for (int c = 0; c < 32; c++) {
            float h = tf * W_embed[10 * 32 + c];
#pragma unroll
            for (int i = 0; i < 10; i++) h += an[i] * W_embed[i * 32 + c];
            g_scalar[n * 32 + c] = h;
        }
    }
    // table: 4 rows per block-iteration (sub-groups of 64 threads)
    // sin(n*theta) via Chebyshev recurrence from ONE sinf/cosf per row
    {
        int sub = tid >> 6;     // 0..3
        int j = tid & 63;       // hidden / output index
        for (int chunk = bid; chunk < (2 * TAB) / 4; chunk += NBLK) {
            __syncthreads();    // protect smf reuse
            int row = chunk * 4 + sub;
            int l = row >> 11;          // TAB=2048
            int i = row & (TAB - 1);
            float r = (float)i * (RMAX / (float)(TAB - 1));
            float rc = fmaxf(r, 1e-9f);
            if (j == 0) {
                const float PI_ = 3.14159265358979323846f;
                float th = PI_ * rc / RMAX;
                smf[1024 + sub * 2 + 0] = sinf(th);
                smf[1024 + sub * 2 + 1] = cosf(th);
            }
            __syncthreads();
            float s1 = smf[1024 + sub * 2 + 0];
            float c2 = 2.0f * smf[1024 + sub * 2 + 1];
            float xr = r / RMAX;
            float xr2 = xr * xr;
            float xr6 = xr2 * xr2 * xr2;
            float f = 1.0f - 28.0f * xr6 + 48.0f * xr6 * xr - 21.0f * xr6 * xr2;
            if (xr >= 1.0f) f = 0.0f;
            const float amp = 0.6324555320336759f;  // sqrt(2/5)
            float g = amp * f / rc;                 // common factor
            float sp = 0.0f, sn = s1;               // sin(0), sin(theta)
            float h = 0.0f;
#pragma unroll
            for (int nb = 0; nb < 8; nb++) {
                h = fmaf(g * sn, W_r1[l * 512 + nb * 64 + j], h);
                float nx = fmaf(c2, sn, -sp);       // sin((n+1)theta)
                sp = sn; sn = nx;
            }
            smf[sub * 64 + j] = h / (1.0f + __expf(-h));  // silu
            __syncthreads();
            int col = ((j >> 1) << 2) | (j & 1);        // only l=0,1 outputs survive
            float acc = 0.0f;
#pragma unroll 8
            for (int h0 = 0; h0 < 64; h0++)
                acc += smf[sub * 64 + h0] * W_r2[l * 8192 + h0 * 128 + col];
            g_rwtab[row * 64 + j] = acc;
        }
    }
    gridbar();

    // ======== P1: edge geometry ========
    for (int e = gtid; e < N_EDGES; e += NBLK * NTHR) {
        int s = ei[e], rc = ei[N_EDGES + e];
        float4 pr = __ldg(&g_pos4[rc]);
        float4 ps = __ldg(&g_pos4[s]);
        float vx = pr.x - ps.x + shifts[e * 3 + 0];
        float vy = pr.y - ps.y + shifts[e * 3 + 1];
        float vz = pr.z - ps.z + shifts[e * 3 + 2];
        float r = sqrtf(vx * vx + vy * vy + vz * vz + 1e-12f);
        float inv = 1.0f / r;
        float tc = r * ((float)(TAB - 1) / RMAX);
        g_vt[e] = make_float4(vx * inv, vy * inv, vz * inv, tc);
        if (r < RMAX) atomicAdd(&g_deg[rc], 1);
    }
    gridbar();

    // ======== P2: scan partials (blocks < NSCB) || table pack (rest) ========
    if (bid < NSCB) {
        int* shi = (int*)smf;
        int i = bid * 256 + tid;
        shi[tid] = (i < N_NODES) ? g_deg[i] : 0;
        __syncthreads();
        for (int off = 128; off; off >>= 1) {
            if (tid < off) shi[tid] += shi[tid + off];
            __syncthreads();
        }
        if (tid == 0) g_part[bid] = shi[0];
    } else {
        int base = (bid - NSCB) * NTHR + tid;
        for (int idx = base; idx < 2 * TAB * 64; idx += (NBLK - NSCB) * NTHR) {
            int row = idx >> 6;
            int il = row & (TAB - 1);
            int j = idx & 63;
            float scale = (j & 1) ? 0.10825317547305482f : 0.0625f;  // sqrt3/16 : 1/16
            float a = g_rwtab[idx] * scale;
            float d = (il < TAB - 1) ? (g_rwtab[idx + 64] * scale - a) : 0.0f;
            g_tabh[idx] = __floats2half2_rn(a, d);
        }
    }
    gridbar();

    // ======== P3: per-chunk offsets + local scan (blocks < NSCB) ========
    if (bid < NSCB) {
        int* shi = (int*)smf;
        int v = (tid < NSCB) ? g_part[tid] : 0;
        int below = (tid < bid) ? v : 0;
#pragma unroll
        for (int o = 16; o; o >>= 1) below += __shfl_xor_sync(0xffffffffu, below, o);
        __shared__ int s_off[8], s_tot[8];
        int w = tid >> 5;
        if ((tid & 31) == 0) s_off[w] = below;
        int totp = v;
#pragma unroll
        for (int o = 16; o; o >>= 1) totp += __shfl_xor_sync(0xffffffffu, totp, o);
        if ((tid & 31) == 0) s_tot[w] = totp;
        __syncthreads();
        int blkoff = 0, total = 0;
#pragma unroll
        for (int q = 0; q < 8; q++) { blkoff += s_off[q]; total += s_tot[q]; }
        int i = bid * 256 + tid;
        int dv = (i < N_NODES) ? g_deg[i] : 0;
        shi[tid] = dv;
        __syncthreads();
        for (int off = 1; off < 256; off <<= 1) {
            int u = (tid >= off) ? shi[tid - off] : 0;
            __syncthreads();
            shi[tid] += u;
            __syncthreads();
        }
        if (i < N_NODES) {
            int excl = shi[tid] - dv + blkoff;
            g_rowptr[i] = excl;
            g_cursor[i] = excl;
        }
        if (bid == NSCB - 1 && tid == 0) g_rowptr[N_NODES] = total;
    }
    gridbar();

    // ======== P4: CSR fill ========
    for (int e = gtid; e < N_EDGES; e += NBLK * NTHR) {
        float4 v = g_vt[e];
        if (v.w >= (float)(TAB - 1)) continue;
        int rc = ei[N_EDGES + e];
        int p = atomicAdd(&g_cursor[rc], 1);
        c_s[p] = ei[e];
        c_u[p] = v;
    }
    gridbar();

    // ======== P5: layer 0 ========
    layer_phase(0, smf, W_mix, W_prod, W_sc, W_ro_s, W_ro_v, eps, batch);
    gridbar();

    // ======== P6: layer 1 (+ loss) ========
    layer_phase(1, smf, W_mix, W_prod, W_sc, W_ro_s, W_ro_v, eps, batch);
    gridbar();

    // ======== P7: final output ========
    if (bid == 0 && tid < G_) {
        float nn = fmaxf((float)g_lcnt[tid], 1.0f);
        out[tid] = 0.5f * g_lacc[tid] / (nn * 13.0f);
    }
}

// ---------------- launcher ----------------
extern "C" void kernel_launch(void* const* d_in, const int* in_sizes, int n_in,
                              void* d_out, int out_size) {
    (void)in_sizes; (void)n_in; (void)out_size;
    k_mega<<<NBLK, NTHR>>>(
        (const float*)d_in[0],  (const float*)d_in[1],  (const float*)d_in[2],
        (const float*)d_in[3],  (const float*)d_in[4],  (const float*)d_in[5],
        (const float*)d_in[6],  (const float*)d_in[7],  (const float*)d_in[8],
        (const float*)d_in[9],  (const float*)d_in[10], (const float*)d_in[11],
        (const float*)d_in[12], (const int*)d_in[13],   (const int*)d_in[14],
        (const int*)d_in[15],   (float*)d_out);
}

// round 7
// speedup vs baseline: 2.6540x; 1.0038x over previous
#include <cuda_runtime.h>
#include <cuda_fp16.h>
#include <math.h>

#define N_NODES 20000
#define N_EDGES 320000
#define G_      64
#define RMAX    5.0f
#define TAB     2048
#define NBLK    592         // 148 SMs x 4 blocks guaranteed resident (64 regs)
#define NTHR    256
#define NWARPS  (NBLK * 8)  // 4736
#define NSCB    79          // ceil(20000/256)

// ---------------- device scratch (static; no allocation) ----------------
__device__ float4 g_pos4[N_NODES];
__device__ float  g_attrs[N_NODES * 10];
__device__ float  g_scalar[N_NODES * 32];
__device__ float  g_pred[N_NODES * 13];
__device__ float4 g_vt[N_EDGES];
__device__ int    g_deg[N_NODES];
__device__ int    g_rowptr[N_NODES + 1];
__device__ int    g_cursor[N_NODES];
__device__ int    g_part[NSCB];
__device__ int    g_wstart[NWARPS + 1];
__device__ int    c_s[N_EDGES];
__device__ float4 c_u[N_EDGES];
__device__ float  g_rwtab[2 * TAB * 64];
__device__ __half2 g_tabh[2 * TAB * 64];
__device__ float  g_lacc[G_];
__device__ int    g_lcnt[G_];

// ---------------- grid barrier (all blocks resident) ----------------
__device__ unsigned g_barArr = 0;
__device__ unsigned g_barGen = 0;

__device__ __forceinline__ void gridbar() {
    __syncthreads();
    if (threadIdx.x == 0) {
        __threadfence();
        unsigned gen = *(volatile unsigned*)&g_barGen;
        unsigned old = atomicAdd(&g_barArr, 1u);
        if (old == NBLK - 1) {
            g_barArr = 0;
            __threadfence();
            atomicAdd(&g_barGen, 1u);
        } else {
            while (*(volatile unsigned*)&g_barGen == gen) __nanosleep(64);
        }
        __threadfence();   // gpu-scope fence -> CCTL.IVALL: invalidates this SM's L1
    }
    __syncthreads();
}

// ---------------- fused layer phase ----------------
__device__ __forceinline__ void layer_phase(int LAYER,
                                            float* Wint, float4* stage,
                                            const float* __restrict__ W_mix,
                                            const float* __restrict__ W_prod,
                                            const float* __restrict__ W_sc,
                                            const float* __restrict__ W_ro_s,
                                            const float* __restrict__ W_ro_v,
                                            const float* __restrict__ eps,
                                            const int* __restrict__ batch) {
    // interleave W_mix[L][0] and W_mix[L][1]: Wint[c*64 + d*2 + which]
    for (int i = threadIdx.x; i < 2048; i += NTHR) {
        int c = i >> 6, r = i & 63, d = r >> 1, which = r & 1;
        Wint[i] = W_mix[LAYER * 4096 + which * 1024 + c * 32 + d];
    }
    __syncthreads();

    int warp = threadIdx.x >> 5, lane = threadIdx.x & 31;
    int w = blockIdx.x * 8 + warp;
    int ns = g_wstart[w], ne = g_wstart[w + 1];
    const float2* tab = (const float2*)(g_tabh + LAYER * TAB * 64);
    float4* mystage = stage + warp * 32;
    float* stage_f = (float*)mystage;

    for (int n = ns; n < ne; n++) {
        float a0 = 0.0f, a1 = 0.0f, a2 = 0.0f, a3 = 0.0f;
        int beg = g_rowptr[n], end = g_rowptr[n + 1];
        if (beg < end) {
            // 1-deep software pipeline
            int sN = __ldg(&c_s[beg]);
            float4 uN = __ldg(&c_u[beg]);
            float scN = __ldg(&g_scalar[sN * 32 + lane]);
            float2 tvN = __ldg(tab + (int)uN.w * 32 + lane);
            for (int p = beg; p < end; p++) {
                float4 u = uN; float sc = scN; float2 tv = tvN;
                if (p + 1 < end) {
                    int s2 = __ldg(&c_s[p + 1]);
                    uN = __ldg(&c_u[p + 1]);
                    scN = __ldg(&g_scalar[s2 * 32 + lane]);
                    tvN = __ldg(tab + (int)uN.w * 32 + lane);
                }
                float fr = u.w - floorf(u.w);
                const __half2* hp = (const __half2*)&tv;
                float2 q0 = __half22float2(hp[0]);
                float2 q1 = __half22float2(hp[1]);
                float m0 = sc * fmaf(fr, q0.y, q0.x);
                float m1 = sc * fmaf(fr, q1.y, q1.x);
                a0 += m0;
                a1 = fmaf(m1, u.x, a1);
                a2 = fmaf(m1, u.y, a2);
                a3 = fmaf(m1, u.z, a3);
            }
        }

        // stage accumulators, mix via broadcast LDS.128
        mystage[lane] = make_float4(a0, a1, a2, a3);
        __syncwarp();
        float f0 = 0.0f, f1 = 0.0f, f2 = 0.0f, f3 = 0.0f;
#pragma unroll
        for (int c = 0; c < 32; c++) {
            float4 av = mystage[c];                       // broadcast
            float2 wv = *(const float2*)&Wint[c * 64 + lane * 2];
            f0 = fmaf(av.x, wv.x, f0);
            f1 = fmaf(av.y, wv.y, f1);
            f2 = fmaf(av.z, wv.y, f2);
            f3 = fmaf(av.w, wv.y, f3);
        }

        float s0 = f0;
        float p = fmaf(fmaf(W_prod[LAYER * 96 + 64 + lane], s0, W_prod[LAYER * 96 + 32 + lane]),
                       s0, W_prod[LAYER * 96 + lane]);
        f0 *= p; f1 *= p; f2 *= p; f3 *= p;

        if (LAYER == 0) {
            float scv = 0.0f;
#pragma unroll
            for (int i = 0; i < 10; i++) scv += g_attrs[n * 10 + i] * W_sc[i * 32 + lane];
            f0 += scv;
        }
        g_scalar[n * 32 + lane] = f0;

        // restage post-poly feats for 13-lane readout
        __syncwarp();
        mystage[lane] = make_float4(f0, f1, f2, f3);
        __syncwarp();

        float e2 = 0.0f;
        if (lane < 13) {
            bool isv = lane >= 10;
            const float* wp = isv ? (W_ro_v + LAYER * 32)
                                  : (W_ro_s + LAYER * 320 + lane);
            int stride = isv ? 1 : 10;
            int comp = isv ? (lane - 9) : 0;
            float acc = 0.0f;
#pragma unroll 8
            for (int c = 0; c < 32; c++)
                acc = fmaf(stage_f[(c << 2) + comp], __ldg(wp + c * stride), acc);
            if (LAYER == 0) {
                g_pred[n * 13 + lane] = acc;
            } else {
                float d = g_pred[n * 13 + lane] + acc - eps[n * 13 + lane];
                e2 = d * d;
            }
        }
        if (LAYER == 1) {
            // sum lanes 0..15 (13..15 are zero)
#pragma unroll
            for (int o = 8; o; o >>= 1) e2 += __shfl_xor_sync(0xffffffffu, e2, o);
            if (lane == 0) {
                int g = batch[n];
                atomicAdd(&g_lacc[g], e2);
                atomicAdd(&g_lcnt[g], 1);
            }
        }
        __syncwarp();   // protect stage before next node overwrites
    }
}

// ---------------- the mega-kernel ----------------
__global__ void __launch_bounds__(NTHR, 4)
k_mega(const float* __restrict__ pos,
       const float* __restrict__ attrs,
       const float* __restrict__ shifts,
       const float* __restrict__ eps,
       const float* __restrict__ alpha_bar,
       const float* __restrict__ W_embed,
       const float* __restrict__ W_r1,
       const float* __restrict__ W_r2,
       const float* __restrict__ W_mix,
       const float* __restrict__ W_sc,
       const float* __restrict__ W_prod,
       const float* __restrict__ W_ro_s,
       const float* __restrict__ W_ro_v,
       const int* __restrict__ ei,
       const int* __restrict__ batch,
       const int* __restrict__ t,
       float* __restrict__ out) {
    __shared__ float smu[2048];        // union: table hid+sincos / scan / Wint
    __shared__ float4 stage[8 * 32];   // per-warp staging (layer phases)
    int tid = threadIdx.x;
    int bid = blockIdx.x;
    int gtid = bid * NTHR + tid;

    // ======== P0: node init + fp32 radial table ========
    if (gtid < N_NODES) {
        int n = gtid;
        if (n < G_) { g_lacc[n] = 0.0f; g_lcnt[n] = 0; }
        g_deg[n] = 0;
        int b = batch[n];
        int tt = t[b];
        float ab = alpha_bar[tt];
        float sa = sqrtf(ab), sb = sqrtf(1.0f - ab);
        g_pos4[n] = make_float4(sa * pos[n * 3 + 0] + sb * eps[n * 13 + 10],
                                sa * pos[n * 3 + 1] + sb * eps[n * 13 + 11],
                                sa * pos[n * 3 + 2] + sb * eps[n * 13 + 12], 0.0f);
        float an[10];
#pragma unroll
        for (int i = 0; i < 10; i++) {
            an[i] = sa * attrs[n * 10 + i] * 0.25f + sb * eps[n * 13 + i];
            g_attrs[n * 10 + i] = an[i];
        }
        float tf = (float)tt / 1000.0f;
#pragma unroll 4
        for (int c = 0; c < 32; c++) {
            float h = tf * W_embed[10 * 32 + c];
#pragma unroll
            for (int i = 0; i < 10; i++) h += an[i] * W_embed[i * 32 + c];
            g_scalar[n * 32 + c] = h;
        }
    }
    // radial table: 4 rows per block-iter; sin(n*th) via Chebyshev recurrence
    {
        int sub = tid >> 6;
        int j = tid & 63;
        for (int chunk = bid; chunk < (2 * TAB) / 4; chunk += NBLK) {
            __syncthreads();
            int row = chunk * 4 + sub;
            int l = row >> 11;
            int i = row & (TAB - 1);
            float r = (float)i * (RMAX / (float)(TAB - 1));
            float rc = fmaxf(r, 1e-9f);
            if (j == 0) {
                const float PI_ = 3.14159265358979323846f;
                float th = PI_ * rc / RMAX;
                smu[1024 + sub * 2 + 0] = sinf(th);
                smu[1024 + sub * 2 + 1] = cosf(th);
            }
            __syncthreads();
            float s1 = smu[1024 + sub * 2 + 0];
            float c2 = 2.0f * smu[1024 + sub * 2 + 1];
            float xr = r / RMAX;
            float xr2 = xr * xr;
            float xr6 = xr2 * xr2 * xr2;
            float f = 1.0f - 28.0f * xr6 + 48.0f * xr6 * xr - 21.0f * xr6 * xr2;
            if (xr >= 1.0f) f = 0.0f;
            float g = 0.6324555320336759f * f / rc;
            float sp = 0.0f, sn = s1;
            float h = 0.0f;
#pragma unroll
            for (int nb = 0; nb < 8; nb++) {
                h = fmaf(g * sn, W_r1[l * 512 + nb * 64 + j], h);
                float nx = fmaf(c2, sn, -sp);
                sp = sn; sn = nx;
            }
            smu[sub * 64 + j] = h / (1.0f + __expf(-h));
            __syncthreads();
            int col = ((j >> 1) << 2) | (j & 1);
            float acc = 0.0f;
#pragma unroll 8
            for (int h0 = 0; h0 < 64; h0++)
                acc += smu[sub * 64 + h0] * W_r2[l * 8192 + h0 * 128 + col];
            g_rwtab[row * 64 + j] = acc;
        }
    }
    gridbar();

    // ======== P1: edge geometry ========
    for (int e = gtid; e < N_EDGES; e += NBLK * NTHR) {
        int s = ei[e], rc = ei[N_EDGES + e];
        float4 pr = __ldg(&g_pos4[rc]);
        float4 ps = __ldg(&g_pos4[s]);
        float vx = pr.x - ps.x + shifts[e * 3 + 0];
        float vy = pr.y - ps.y + shifts[e * 3 + 1];
        float vz = pr.z - ps.z + shifts[e * 3 + 2];
        float r = sqrtf(vx * vx + vy * vy + vz * vz + 1e-12f);
        float inv = 1.0f / r;
        float tc = r * ((float)(TAB - 1) / RMAX);
        g_vt[e] = make_float4(vx * inv, vy * inv, vz * inv, tc);
        if (r < RMAX) atomicAdd(&g_deg[rc], 1);
    }
    gridbar();

    // ======== P2: scan partials (blocks < NSCB) || table pack (rest) ========
    if (bid < NSCB) {
        int* shi = (int*)smu;
        int i = bid * 256 + tid;
        shi[tid] = (i < N_NODES) ? g_deg[i] : 0;
        __syncthreads();
        for (int off = 128; off; off >>= 1) {
            if (tid < off) shi[tid] += shi[tid + off];
            __syncthreads();
        }
        if (tid == 0) g_part[bid] = shi[0];
    } else {
        int base = (bid - NSCB) * NTHR + tid;
        for (int idx = base; idx < 2 * TAB * 64; idx += (NBLK - NSCB) * NTHR) {
            int row = idx >> 6;
            int il = row & (TAB - 1);
            int j = idx & 63;
            float scale = (j & 1) ? 0.10825317547305482f : 0.0625f;
            float a = g_rwtab[idx] * scale;
            float d = (il < TAB - 1) ? (g_rwtab[idx + 64] * scale - a) : 0.0f;
            g_tabh[idx] = __floats2half2_rn(a, d);
        }
    }
    gridbar();

    // ======== P3: per-chunk offsets + local scan (blocks < NSCB) ========
    if (bid < NSCB) {
        int* shi = (int*)smu;
        int v = (tid < NSCB) ? g_part[tid] : 0;
        int below = (tid < bid) ? v : 0;
#pragma unroll
        for (int o = 16; o; o >>= 1) below += __shfl_xor_sync(0xffffffffu, below, o);
        __shared__ int s_off[8], s_tot[8];
        int w = tid >> 5;
        if ((tid & 31) == 0) s_off[w] = below;
        int totp = v;
#pragma unroll
        for (int o = 16; o; o >>= 1) totp += __shfl_xor_sync(0xffffffffu, totp, o);
        if ((tid & 31) == 0) s_tot[w] = totp;
        __syncthreads();
        int blkoff = 0, total = 0;
#pragma unroll
        for (int q = 0; q < 8; q++) { blkoff += s_off[q]; total += s_tot[q]; }
        int i = bid * 256 + tid;
        int dv = (i < N_NODES) ? g_deg[i] : 0;
        shi[tid] = dv;
        __syncthreads();
        for (int off = 1; off < 256; off <<= 1) {
            int u = (tid >= off) ? shi[tid - off] : 0;
            __syncthreads();
            shi[tid] += u;
            __syncthreads();
        }
        if (i < N_NODES) {
            int excl = shi[tid] - dv + blkoff;
            g_rowptr[i] = excl;
            g_cursor[i] = excl;
        }
        if (bid == NSCB - 1 && tid == 0) g_rowptr[N_NODES] = total;
    }
    gridbar();

    // ======== P4: CSR fill + cost-balanced warp partition ========
    if (gtid <= NWARPS) {
        int tot = g_rowptr[N_NODES];
        int F = tot + 16 * N_NODES;
        int target = (int)(((long long)gtid * F) / NWARPS);
        int lo = 0, hi = N_NODES;
        while (lo < hi) {
            int mid = (lo + hi) >> 1;
            int key = g_rowptr[mid] + 16 * mid;
            if (key >= target) hi = mid; else lo = mid + 1;
        }
        g_wstart[gtid] = lo;
    }
    for (int e = gtid; e < N_EDGES; e += NBLK * NTHR) {
        float4 v = g_vt[e];
        if (v.w >= (float)(TAB - 1)) continue;
        int rc = ei[N_EDGES + e];
        int p = atomicAdd(&g_cursor[rc], 1);
        c_s[p] = ei[e];
        c_u[p] = v;
    }
    gridbar();

    // ======== P5: layer 0 ========
    layer_phase(0, smu, stage, W_mix, W_prod, W_sc, W_ro_s, W_ro_v, eps, batch);
    gridbar();

    // ======== P6: layer 1 (+ loss) ========
    layer_phase(1, smu, stage, W_mix, W_prod, W_sc, W_ro_s, W_ro_v, eps, batch);
    gridbar();

    // ======== P7: final output ========
    if (bid == 0 && tid < G_) {
        float nn = fmaxf((float)g_lcnt[tid], 1.0f);
        out[tid] = 0.5f * g_lacc[tid] / (nn * 13.0f);
    }
}

// ---------------- launcher ----------------
extern "C" void kernel_launch(void* const* d_in, const int* in_sizes, int n_in,
                              void* d_out, int out_size) {
    (void)in_sizes; (void)n_in; (void)out_size;
    k_mega<<<NBLK, NTHR>>>(
        (const float*)d_in[0],  (const float*)d_in[1],  (const float*)d_in[2],
        (const float*)d_in[3],  (const float*)d_in[4],  (const float*)d_in[5],
        (const float*)d_in[6],  (const float*)d_in[7],  (const float*)d_in[8],
        (const float*)d_in[9],  (const float*)d_in[10], (const float*)d_in[11],
        (const float*)d_in[12], (const int*)d_in[13],   (const int*)d_in[14],
        (const int*)d_in[15],   (float*)d_out);
}